// round 13
// baseline (speedup 1.0000x reference)
#include <cuda_runtime.h>
#include <cuda_fp16.h>
#include <cstdint>

// Problem constants (fixed by the dataset)
#define NN   50000
#define EE   800000
#define NF   256
#define NH   128
#define NO   64
#define NB   ((NN + 255) / 256)   // 196 scan blocks

// ---------------- scratch (no allocations allowed) ----------------
__device__ int    g_deg[NN];
__device__ int    g_cursor[NN];
__device__ float  g_dis[NN];
__device__ int    g_off[NN + 1];
__device__ int    g_bsum[NB];
__device__ int    g_bbase[NB];
__device__ int2   g_csre[EE];               // (src, norm-bits) packed
__device__ __half g_h1h[(size_t)NN * NH];   // x @ W1 (fp16 storage)
__device__ float  g_hr[(size_t)NN * NH];    // relu(agg1 + b1)
__device__ __half g_h2h[(size_t)NN * NO];   // hr @ W2 (fp16 storage)

// ---------------- packed f32x2 helpers ----------------
__device__ __forceinline__ unsigned long long pack2(float lo, float hi) {
    unsigned long long r;
    asm("mov.b64 %0, {%1, %2};" : "=l"(r) : "f"(lo), "f"(hi));
    return r;
}
__device__ __forceinline__ void unpack2(unsigned long long v, float& lo, float& hi) {
    asm("mov.b64 {%0, %1}, %2;" : "=f"(lo), "=f"(hi) : "l"(v));
}
__device__ __forceinline__ unsigned long long fma2(unsigned long long a,
                                                   unsigned long long b,
                                                   unsigned long long c) {
    unsigned long long d;
    asm("fma.rn.f32x2 %0, %1, %2, %3;" : "=l"(d) : "l"(a), "l"(b), "l"(c));
    return d;
}

// ---------------- small graph-prep kernels ----------------
__global__ void k_zero_deg() {
    int i = blockIdx.x * blockDim.x + threadIdx.x;
    if (i < NN) g_deg[i] = 0;
}

// edge_index is int32
__global__ void k_hist(const int* __restrict__ ei, int E, int n) {
    int e = blockIdx.x * blockDim.x + threadIdx.x;
    if (e < E) {
        int d = ei[E + e];
        if ((unsigned)d < (unsigned)n) atomicAdd(&g_deg[d], 1);
    }
}

__global__ void k_blocksum(int n) {
    __shared__ int sh[256];
    int i = blockIdx.x * 256 + threadIdx.x;
    sh[threadIdx.x] = (i < n) ? g_deg[i] : 0;
    __syncthreads();
    for (int s = 128; s > 0; s >>= 1) {
        if (threadIdx.x < s) sh[threadIdx.x] += sh[threadIdx.x + s];
        __syncthreads();
    }
    if (threadIdx.x == 0) g_bsum[blockIdx.x] = sh[0];
}

// parallel exclusive scan of block sums (nb <= 256), single block
__global__ void k_scan_bases(int nb) {
    __shared__ int sh[256];
    int t = threadIdx.x;
    int v = (t < nb) ? g_bsum[t] : 0;
    sh[t] = v;
    __syncthreads();
    for (int o = 1; o < 256; o <<= 1) {
        int u = (t >= o) ? sh[t - o] : 0;
        __syncthreads();
        sh[t] += u;
        __syncthreads();
    }
    if (t < nb) g_bbase[t] = sh[t] - v;   // exclusive
}

__global__ void k_offsets(int n) {
    __shared__ int sh[256];
    int tid = threadIdx.x;
    int i = blockIdx.x * 256 + tid;
    int v = (i < n) ? g_deg[i] : 0;
    sh[tid] = v;
    __syncthreads();
    for (int ofs = 1; ofs < 256; ofs <<= 1) {
        int t = (tid >= ofs) ? sh[tid - ofs] : 0;
        __syncthreads();
        sh[tid] += t;
        __syncthreads();
    }
    if (i < n) {
        int base = g_bbase[blockIdx.x];
        g_off[i] = base + sh[tid] - v;
        g_dis[i] = (v > 0) ? rsqrtf((float)v) : 0.0f;
        g_cursor[i] = 0;
        if (i == n - 1) g_off[n] = base + sh[tid];
    }
}

__global__ void k_fill(const int* __restrict__ ei, int E, int n) {
    int e = blockIdx.x * blockDim.x + threadIdx.x;
    if (e < E) {
        int s = ei[e];
        int d = ei[E + e];
        if ((unsigned)s < (unsigned)n && (unsigned)d < (unsigned)n) {
            int pos = g_off[d] + atomicAdd(&g_cursor[d], 1);
            float nm = g_dis[s] * g_dis[d];
            g_csre[pos] = make_int2(s, __float_as_int(nm));
        }
    }
}

// ---------------- double-buffered register-tiled SGEMM (fma.f32x2) -------------
// C[M,N] = A[M,K] @ B[K,N], row-major, K % BK == 0, N == BN.
// HALF_OUT: C is __half* (row stride N halves); otherwise float*.
template <int BM, int BN, int BK, int TM, int TN, bool HALF_OUT>
__device__ __forceinline__ void gemm_body(const float* __restrict__ A,
                                          const float* __restrict__ B,
                                          void* __restrict__ Cv,
                                          int M, int N, int K) {
    constexpr int NTH = (BM / TM) * (BN / TN);
    constexpr int LA = BM * BK / (4 * NTH);
    constexpr int LB = BK * BN / (4 * NTH);
    __shared__ __align__(16) float As[2][BK][BM];   // transposed
    __shared__ __align__(16) float Bs[2][BK][BN];

    const int tid = threadIdx.x;
    const int blockRow = blockIdx.x;
    const int tCol = tid % (BN / TN);
    const int tRow = tid / (BN / TN);

    float4 ra[LA], rb[LB];

    auto ldg_tile = [&](int k0) {
#pragma unroll
        for (int t = 0; t < LA; t++) {
            int i = tid + t * NTH;
            int r = i / (BK / 4);
            int kv = i % (BK / 4);
            int gr = blockRow * BM + r;
            ra[t] = (gr < M) ? *(const float4*)(A + (size_t)gr * K + k0 + kv * 4)
                             : make_float4(0.f, 0.f, 0.f, 0.f);
        }
#pragma unroll
        for (int t = 0; t < LB; t++) {
            int i = tid + t * NTH;
            int r = i / (BN / 4);
            int cv = i % (BN / 4);
            rb[t] = *(const float4*)(B + (size_t)(k0 + r) * N + cv * 4);
        }
    };
    auto sts_tile = [&](int buf) {
#pragma unroll
        for (int t = 0; t < LA; t++) {
            int i = tid + t * NTH;
            int r = i / (BK / 4);
            int kv = i % (BK / 4);
            As[buf][kv * 4 + 0][r] = ra[t].x;
            As[buf][kv * 4 + 1][r] = ra[t].y;
            As[buf][kv * 4 + 2][r] = ra[t].z;
            As[buf][kv * 4 + 3][r] = ra[t].w;
        }
#pragma unroll
        for (int t = 0; t < LB; t++) {
            int i = tid + t * NTH;
            int r = i / (BN / 4);
            int cv = i % (BN / 4);
            *(float4*)&Bs[buf][r][cv * 4] = rb[t];
        }
    };

    unsigned long long acc[TM][TN / 2];
#pragma unroll
    for (int i = 0; i < TM; i++)
#pragma unroll
        for (int j = 0; j < TN / 2; j++) acc[i][j] = 0ull;

    const int nk = K / BK;
    ldg_tile(0);
    sts_tile(0);
    __syncthreads();

    for (int kb = 0; kb < nk; kb++) {
        const int cur = kb & 1;
        if (kb + 1 < nk) ldg_tile((kb + 1) * BK);

#pragma unroll
        for (int kk = 0; kk < BK; kk++) {
            float4 a0 = *(const float4*)&As[cur][kk][tRow * TM];
            float4 a1 = *(const float4*)&As[cur][kk][tRow * TM + 4];
            unsigned long long m2[TM];
            m2[0] = pack2(a0.x, a0.x); m2[1] = pack2(a0.y, a0.y);
            m2[2] = pack2(a0.z, a0.z); m2[3] = pack2(a0.w, a0.w);
            m2[4] = pack2(a1.x, a1.x); m2[5] = pack2(a1.y, a1.y);
            m2[6] = pack2(a1.z, a1.z); m2[7] = pack2(a1.w, a1.w);
            unsigned long long b2r[TN / 2];
            const unsigned long long* bp =
                (const unsigned long long*)&Bs[cur][kk][tCol * TN];
#pragma unroll
            for (int j = 0; j < TN / 2; j++) b2r[j] = bp[j];
#pragma unroll
            for (int i = 0; i < TM; i++)
#pragma unroll
                for (int j = 0; j < TN / 2; j++)
                    acc[i][j] = fma2(m2[i], b2r[j], acc[i][j]);
        }

        if (kb + 1 < nk) {
            __syncthreads();
            sts_tile(cur ^ 1);
            __syncthreads();
        }
    }

#pragma unroll
    for (int i = 0; i < TM; i++) {
        int gr = blockRow * BM + tRow * TM + i;
        if (gr >= M) continue;
        if (HALF_OUT) {
            __half* Ch = (__half*)Cv;
            uint4 pk;
            float a0, a1, a2, a3, a4, a5, a6, a7;
            unpack2(acc[i][0], a0, a1);
            unpack2(acc[i][1], a2, a3);
            unpack2(acc[i][2], a4, a5);
            unpack2(acc[i][3], a6, a7);
            __half2 p0 = __floats2half2_rn(a0, a1);
            __half2 p1 = __floats2half2_rn(a2, a3);
            __half2 p2 = __floats2half2_rn(a4, a5);
            __half2 p3 = __floats2half2_rn(a6, a7);
            pk.x = *(uint32_t*)&p0; pk.y = *(uint32_t*)&p1;
            pk.z = *(uint32_t*)&p2; pk.w = *(uint32_t*)&p3;
            *(uint4*)(Ch + (size_t)gr * N + tCol * TN) = pk;
        } else {
            float* C = (float*)Cv;
#pragma unroll
            for (int j = 0; j < TN / 2; j += 2) {
                float a0, a1, a2, a3;
                unpack2(acc[i][j], a0, a1);
                unpack2(acc[i][j + 1], a2, a3);
                *(float4*)(C + (size_t)gr * N + tCol * TN + 2 * j) =
                    make_float4(a0, a1, a2, a3);
            }
        }
    }
}

// ---------------- SpMM1: 2 rows/warp, uint4 fp16 gather, fp32 accumulate -----
__global__ void k_spmm1(const float* __restrict__ b1, int n) {
    const int gw   = blockIdx.x * (blockDim.x / 32) + (threadIdx.x >> 5);
    const int lane = threadIdx.x & 31;
    const int sub  = lane >> 4;          // 2 rows per warp
    const int li   = lane & 15;          // 16 lanes x 8 cols = 128 cols
    const int row  = gw * 2 + sub;
    if (row >= n) return;

    const uint4* Hp = (const uint4*)g_h1h;   // 128 halves/row = 16 uint4
    const int s = g_off[row];
    const int e = g_off[row + 1];
    float acc0[8] = {0.f, 0.f, 0.f, 0.f, 0.f, 0.f, 0.f, 0.f};
    float acc1[8] = {0.f, 0.f, 0.f, 0.f, 0.f, 0.f, 0.f, 0.f};
    int p = s;
    for (; p + 2 <= e; p += 2) {
        int2  e0 = g_csre[p];
        int2  e1 = g_csre[p + 1];
        float n0 = __int_as_float(e0.y);
        float n1 = __int_as_float(e1.y);
        uint4 v0 = Hp[(size_t)e0.x * 16 + li];
        uint4 v1 = Hp[(size_t)e1.x * 16 + li];
        const uint32_t* w0 = &v0.x;
        const uint32_t* w1 = &v1.x;
#pragma unroll
        for (int j = 0; j < 4; j++) {
            float2 f0 = __half22float2(*(__half2*)&w0[j]);
            float2 f1 = __half22float2(*(__half2*)&w1[j]);
            acc0[2 * j + 0] = fmaf(n0, f0.x, acc0[2 * j + 0]);
            acc0[2 * j + 1] = fmaf(n0, f0.y, acc0[2 * j + 1]);
            acc1[2 * j + 0] = fmaf(n1, f1.x, acc1[2 * j + 0]);
            acc1[2 * j + 1] = fmaf(n1, f1.y, acc1[2 * j + 1]);
        }
    }
    if (p < e) {
        int2  e0 = g_csre[p];
        float n0 = __int_as_float(e0.y);
        uint4 v0 = Hp[(size_t)e0.x * 16 + li];
        const uint32_t* w0 = &v0.x;
#pragma unroll
        for (int j = 0; j < 4; j++) {
            float2 f0 = __half22float2(*(__half2*)&w0[j]);
            acc0[2 * j + 0] = fmaf(n0, f0.x, acc0[2 * j + 0]);
            acc0[2 * j + 1] = fmaf(n0, f0.y, acc0[2 * j + 1]);
        }
    }
    float4 ba = *(const float4*)(b1 + li * 8);
    float4 bb = *(const float4*)(b1 + li * 8 + 4);
    float4 o0, o1;
    o0.x = fmaxf(acc0[0] + acc1[0] + ba.x, 0.f);
    o0.y = fmaxf(acc0[1] + acc1[1] + ba.y, 0.f);
    o0.z = fmaxf(acc0[2] + acc1[2] + ba.z, 0.f);
    o0.w = fmaxf(acc0[3] + acc1[3] + ba.w, 0.f);
    o1.x = fmaxf(acc0[4] + acc1[4] + bb.x, 0.f);
    o1.y = fmaxf(acc0[5] + acc1[5] + bb.y, 0.f);
    o1.z = fmaxf(acc0[6] + acc1[6] + bb.z, 0.f);
    o1.w = fmaxf(acc0[7] + acc1[7] + bb.w, 0.f);
    *(float4*)(g_hr + (size_t)row * NH + li * 8)     = o0;
    *(float4*)(g_hr + (size_t)row * NH + li * 8 + 4) = o1;
}

// ---------------- SpMM2: fp16 gather of h2 (2 rows per warp) ------------------
__global__ void k_spmm2(const float* __restrict__ b2, float* __restrict__ out, int n) {
    const int gw   = blockIdx.x * (blockDim.x / 32) + (threadIdx.x >> 5);
    const int lane = threadIdx.x & 31;
    const int sub  = lane >> 4;          // 2 rows per warp
    const int li   = lane & 15;          // 16 lanes x 4 cols = 64 cols
    const int row  = gw * 2 + sub;
    if (row >= n) return;

    const uint2* Hp = (const uint2*)g_h2h;   // 64 halves/row = 16 uint2
    const int s = g_off[row];
    const int e = g_off[row + 1];
    float4 acc0 = make_float4(0.f, 0.f, 0.f, 0.f);
    float4 acc1 = make_float4(0.f, 0.f, 0.f, 0.f);
    int p = s;
    for (; p + 2 <= e; p += 2) {
        int2  e0 = g_csre[p];
        int2  e1 = g_csre[p + 1];
        float n0 = __int_as_float(e0.y);
        float n1 = __int_as_float(e1.y);
        uint2 v0 = Hp[(size_t)e0.x * 16 + li];
        uint2 v1 = Hp[(size_t)e1.x * 16 + li];
        float2 f00 = __half22float2(*(__half2*)&v0.x);
        float2 f01 = __half22float2(*(__half2*)&v0.y);
        float2 f10 = __half22float2(*(__half2*)&v1.x);
        float2 f11 = __half22float2(*(__half2*)&v1.y);
        acc0.x = fmaf(n0, f00.x, acc0.x); acc1.x = fmaf(n1, f10.x, acc1.x);
        acc0.y = fmaf(n0, f00.y, acc0.y); acc1.y = fmaf(n1, f10.y, acc1.y);
        acc0.z = fmaf(n0, f01.x, acc0.z); acc1.z = fmaf(n1, f11.x, acc1.z);
        acc0.w = fmaf(n0, f01.y, acc0.w); acc1.w = fmaf(n1, f11.y, acc1.w);
    }
    if (p < e) {
        int2  e0 = g_csre[p];
        float n0 = __int_as_float(e0.y);
        uint2 v0 = Hp[(size_t)e0.x * 16 + li];
        float2 f00 = __half22float2(*(__half2*)&v0.x);
        float2 f01 = __half22float2(*(__half2*)&v0.y);
        acc0.x = fmaf(n0, f00.x, acc0.x);
        acc0.y = fmaf(n0, f00.y, acc0.y);
        acc0.z = fmaf(n0, f01.x, acc0.z);
        acc0.w = fmaf(n0, f01.y, acc0.w);
    }
    float4 b = *(const float4*)(b2 + li * 4);
    acc0.x += acc1.x + b.x;
    acc0.y += acc1.y + b.y;
    acc0.z += acc1.z + b.z;
    acc0.w += acc1.w + b.w;
    *(float4*)(out + (size_t)row * NO + li * 4) = acc0;
}

// ---------------- thin wrappers binding __device__ globals ----------------
// GEMM1: BM=64 (782 CTAs, 128 thr), plain A smem, fp16 out.
__global__ void __launch_bounds__(128) k_gemm1(const float* __restrict__ x,
                                               const float* __restrict__ W1, int n) {
    gemm_body<64, 128, 16, 8, 8, true>(x, W1, g_h1h, n, NH, NF);
}
// GEMM2: BK=32, plain A smem, fp16 out.
__global__ void __launch_bounds__(128) k_gemm2(const float* __restrict__ W2, int n) {
    gemm_body<128, 64, 32, 8, 8, true>(g_hr, W2, g_h2h, n, NO, NH);
}

// ---------------- launcher ----------------
extern "C" void kernel_launch(void* const* d_in, const int* in_sizes, int n_in,
                              void* d_out, int out_size) {
    const float* x  = (const float*)d_in[0];
    const int*   ei = (const int*)d_in[1];     // int32 edge_index [2, E]
    const float* W1 = (const float*)d_in[2];
    const float* b1 = (const float*)d_in[3];
    const float* W2 = (const float*)d_in[4];
    const float* b2 = (const float*)d_in[5];
    float* out = (float*)d_out;

    const int n = in_sizes[0] / NF;   // 50000
    const int E = in_sizes[1] / 2;    // 800000
    const int nb = (n + 255) / 256;

    // Lazily-created side stream + events (host objects only; created once).
    static cudaStream_t s2 = nullptr;
    static cudaEvent_t evRoot = nullptr, evG = nullptr;
    static bool tried = false;
    if (!tried) {
        tried = true;
        bool ok = (cudaStreamCreateWithFlags(&s2, cudaStreamNonBlocking) == cudaSuccess);
        ok = ok && (cudaEventCreateWithFlags(&evRoot, cudaEventDisableTiming) == cudaSuccess);
        ok = ok && (cudaEventCreateWithFlags(&evG,    cudaEventDisableTiming) == cudaSuccess);
        if (!ok) s2 = nullptr;
    }
    const bool fork = (s2 != nullptr);
    cudaStream_t sg = fork ? s2 : (cudaStream_t)0;

    // Fork point recorded BEFORE any prep launch: gemm1 depends only on evRoot,
    // so it runs parallel with the prep chain regardless of API call order.
    if (fork) {
        cudaEventRecord(evRoot, 0);
        cudaStreamWaitEvent(s2, evRoot, 0);
    }

    // ---- graph prep (part 1) on main stream ----
    k_zero_deg<<<(n + 255) / 256, 256>>>();                 // launch idx 0
    k_hist<<<(E + 255) / 256, 256>>>(ei, E, n);             // idx 1
    k_blocksum<<<nb, 256>>>(n);                             // idx 2

    // ---- GEMM1 as the 4th kernel launch (idx 3) so ncu's capture window
    //      lands on it; dependency-wise still parallel with all prep. ----
    k_gemm1<<<(n + 63) / 64, 128, 0, sg>>>(x, W1, n);       // idx 3
    if (fork) cudaEventRecord(evG, s2);

    // ---- graph prep (part 2) on main stream ----
    k_scan_bases<<<1, 256>>>(nb);                           // idx 4
    k_offsets<<<nb, 256>>>(n);                              // idx 5
    k_fill<<<(E + 255) / 256, 256>>>(ei, E, n);             // idx 6

    // ---- join: SpMM1 needs both h1 and the CSR ----
    if (fork) cudaStreamWaitEvent(0, evG, 0);
    k_spmm1<<<(n / 2 + 7) / 8, 256>>>(b1, n);
    // layer 2: h2 = hr @ W2 ; out = Ahat @ h2 + b2
    k_gemm2<<<(n + 127) / 128, 128>>>(W2, n);
    k_spmm2<<<(n / 2 + 7) / 8, 256>>>(b2, out, n);
}

// round 14
// speedup vs baseline: 1.0022x; 1.0022x over previous
#include <cuda_runtime.h>
#include <cuda_fp16.h>
#include <cstdint>

// Problem constants (fixed by the dataset)
#define NN   50000
#define EE   800000
#define NF   256
#define NH   128
#define NO   64
#define NB   ((NN + 255) / 256)   // 196 scan blocks

// ---------------- scratch (no allocations allowed) ----------------
__device__ int    g_deg[NN];
__device__ int    g_cursor[NN];
__device__ float  g_dis[NN];
__device__ int    g_off[NN + 1];
__device__ int    g_bsum[NB];
__device__ int    g_bbase[NB];
__device__ int2   g_csre[EE];               // (src, norm-bits) packed
__device__ __half g_h1h[(size_t)NN * NH];   // x @ W1 (fp16 storage)
__device__ float  g_hr[(size_t)NN * NH];    // relu(agg1 + b1)
__device__ __half g_h2h[(size_t)NN * NO];   // hr @ W2 (fp16 storage)

// ---------------- packed f32x2 helpers ----------------
__device__ __forceinline__ unsigned long long pack2(float lo, float hi) {
    unsigned long long r;
    asm("mov.b64 %0, {%1, %2};" : "=l"(r) : "f"(lo), "f"(hi));
    return r;
}
__device__ __forceinline__ void unpack2(unsigned long long v, float& lo, float& hi) {
    asm("mov.b64 {%0, %1}, %2;" : "=f"(lo), "=f"(hi) : "l"(v));
}
__device__ __forceinline__ unsigned long long fma2(unsigned long long a,
                                                   unsigned long long b,
                                                   unsigned long long c) {
    unsigned long long d;
    asm("fma.rn.f32x2 %0, %1, %2, %3;" : "=l"(d) : "l"(a), "l"(b), "l"(c));
    return d;
}

// ---------------- small graph-prep kernels ----------------
__global__ void k_zero_deg() {
    int i = blockIdx.x * blockDim.x + threadIdx.x;
    if (i < NN) g_deg[i] = 0;
}

// edge_index is int32
__global__ void k_hist(const int* __restrict__ ei, int E, int n) {
    int e = blockIdx.x * blockDim.x + threadIdx.x;
    if (e < E) {
        int d = ei[E + e];
        if ((unsigned)d < (unsigned)n) atomicAdd(&g_deg[d], 1);
    }
}

__global__ void k_blocksum(int n) {
    __shared__ int sh[256];
    int i = blockIdx.x * 256 + threadIdx.x;
    sh[threadIdx.x] = (i < n) ? g_deg[i] : 0;
    __syncthreads();
    for (int s = 128; s > 0; s >>= 1) {
        if (threadIdx.x < s) sh[threadIdx.x] += sh[threadIdx.x + s];
        __syncthreads();
    }
    if (threadIdx.x == 0) g_bsum[blockIdx.x] = sh[0];
}

// parallel exclusive scan of block sums (nb <= 256), single block
__global__ void k_scan_bases(int nb) {
    __shared__ int sh[256];
    int t = threadIdx.x;
    int v = (t < nb) ? g_bsum[t] : 0;
    sh[t] = v;
    __syncthreads();
    for (int o = 1; o < 256; o <<= 1) {
        int u = (t >= o) ? sh[t - o] : 0;
        __syncthreads();
        sh[t] += u;
        __syncthreads();
    }
    if (t < nb) g_bbase[t] = sh[t] - v;   // exclusive
}

__global__ void k_offsets(int n) {
    __shared__ int sh[256];
    int tid = threadIdx.x;
    int i = blockIdx.x * 256 + tid;
    int v = (i < n) ? g_deg[i] : 0;
    sh[tid] = v;
    __syncthreads();
    for (int ofs = 1; ofs < 256; ofs <<= 1) {
        int t = (tid >= ofs) ? sh[tid - ofs] : 0;
        __syncthreads();
        sh[tid] += t;
        __syncthreads();
    }
    if (i < n) {
        int base = g_bbase[blockIdx.x];
        g_off[i] = base + sh[tid] - v;
        g_dis[i] = (v > 0) ? rsqrtf((float)v) : 0.0f;
        g_cursor[i] = 0;
        if (i == n - 1) g_off[n] = base + sh[tid];
    }
}

__global__ void k_fill(const int* __restrict__ ei, int E, int n) {
    int e = blockIdx.x * blockDim.x + threadIdx.x;
    if (e < E) {
        int s = ei[e];
        int d = ei[E + e];
        if ((unsigned)s < (unsigned)n && (unsigned)d < (unsigned)n) {
            int pos = g_off[d] + atomicAdd(&g_cursor[d], 1);
            float nm = g_dis[s] * g_dis[d];
            g_csre[pos] = make_int2(s, __float_as_int(nm));
        }
    }
}

// ---------------- double-buffered register-tiled SGEMM (fma.f32x2) -------------
// C[M,N] = A[M,K] @ B[K,N], row-major, K % BK == 0, N == BN.
// Single __syncthreads per k-slab (compute(cur) then sts(nxt) touch disjoint
// buffers; previous barrier ordered the handoff).
// HALF_OUT: C is __half* (row stride N halves); otherwise float*.
template <int BM, int BN, int BK, int TM, int TN, bool HALF_OUT>
__device__ __forceinline__ void gemm_body(const float* __restrict__ A,
                                          const float* __restrict__ B,
                                          void* __restrict__ Cv,
                                          int M, int N, int K) {
    constexpr int NTH = (BM / TM) * (BN / TN);
    constexpr int LA = BM * BK / (4 * NTH);
    constexpr int LB = BK * BN / (4 * NTH);
    __shared__ __align__(16) float As[2][BK][BM];   // transposed
    __shared__ __align__(16) float Bs[2][BK][BN];

    const int tid = threadIdx.x;
    const int blockRow = blockIdx.x;
    const int tCol = tid % (BN / TN);
    const int tRow = tid / (BN / TN);

    float4 ra[LA], rb[LB];

    auto ldg_tile = [&](int k0) {
#pragma unroll
        for (int t = 0; t < LA; t++) {
            int i = tid + t * NTH;
            int r = i / (BK / 4);
            int kv = i % (BK / 4);
            int gr = blockRow * BM + r;
            ra[t] = (gr < M) ? *(const float4*)(A + (size_t)gr * K + k0 + kv * 4)
                             : make_float4(0.f, 0.f, 0.f, 0.f);
        }
#pragma unroll
        for (int t = 0; t < LB; t++) {
            int i = tid + t * NTH;
            int r = i / (BN / 4);
            int cv = i % (BN / 4);
            rb[t] = *(const float4*)(B + (size_t)(k0 + r) * N + cv * 4);
        }
    };
    auto sts_tile = [&](int buf) {
#pragma unroll
        for (int t = 0; t < LA; t++) {
            int i = tid + t * NTH;
            int r = i / (BK / 4);
            int kv = i % (BK / 4);
            As[buf][kv * 4 + 0][r] = ra[t].x;
            As[buf][kv * 4 + 1][r] = ra[t].y;
            As[buf][kv * 4 + 2][r] = ra[t].z;
            As[buf][kv * 4 + 3][r] = ra[t].w;
        }
#pragma unroll
        for (int t = 0; t < LB; t++) {
            int i = tid + t * NTH;
            int r = i / (BN / 4);
            int cv = i % (BN / 4);
            *(float4*)&Bs[buf][r][cv * 4] = rb[t];
        }
    };

    unsigned long long acc[TM][TN / 2];
#pragma unroll
    for (int i = 0; i < TM; i++)
#pragma unroll
        for (int j = 0; j < TN / 2; j++) acc[i][j] = 0ull;

    const int nk = K / BK;
    ldg_tile(0);
    sts_tile(0);
    __syncthreads();

    for (int kb = 0; kb < nk; kb++) {
        const int cur = kb & 1;
        if (kb + 1 < nk) ldg_tile((kb + 1) * BK);

#pragma unroll
        for (int kk = 0; kk < BK; kk++) {
            float4 a0 = *(const float4*)&As[cur][kk][tRow * TM];
            float4 a1 = *(const float4*)&As[cur][kk][tRow * TM + 4];
            unsigned long long m2[TM];
            m2[0] = pack2(a0.x, a0.x); m2[1] = pack2(a0.y, a0.y);
            m2[2] = pack2(a0.z, a0.z); m2[3] = pack2(a0.w, a0.w);
            m2[4] = pack2(a1.x, a1.x); m2[5] = pack2(a1.y, a1.y);
            m2[6] = pack2(a1.z, a1.z); m2[7] = pack2(a1.w, a1.w);
            // B row: 8 consecutive floats = 2x LDS.128
            unsigned long long b2r[TN / 2];
            const ulonglong2* bp =
                (const ulonglong2*)&Bs[cur][kk][tCol * TN];
            ulonglong2 q0 = bp[0];
            ulonglong2 q1 = bp[1];
            b2r[0] = q0.x; b2r[1] = q0.y; b2r[2] = q1.x; b2r[3] = q1.y;
#pragma unroll
            for (int i = 0; i < TM; i++)
#pragma unroll
                for (int j = 0; j < TN / 2; j++)
                    acc[i][j] = fma2(m2[i], b2r[j], acc[i][j]);
        }

        if (kb + 1 < nk) {
            sts_tile(cur ^ 1);      // disjoint buffer from the one just read
            __syncthreads();        // single barrier per slab
        }
    }

#pragma unroll
    for (int i = 0; i < TM; i++) {
        int gr = blockRow * BM + tRow * TM + i;
        if (gr >= M) continue;
        if (HALF_OUT) {
            __half* Ch = (__half*)Cv;
            uint4 pk;
            float a0, a1, a2, a3, a4, a5, a6, a7;
            unpack2(acc[i][0], a0, a1);
            unpack2(acc[i][1], a2, a3);
            unpack2(acc[i][2], a4, a5);
            unpack2(acc[i][3], a6, a7);
            __half2 p0 = __floats2half2_rn(a0, a1);
            __half2 p1 = __floats2half2_rn(a2, a3);
            __half2 p2 = __floats2half2_rn(a4, a5);
            __half2 p3 = __floats2half2_rn(a6, a7);
            pk.x = *(uint32_t*)&p0; pk.y = *(uint32_t*)&p1;
            pk.z = *(uint32_t*)&p2; pk.w = *(uint32_t*)&p3;
            *(uint4*)(Ch + (size_t)gr * N + tCol * TN) = pk;
        } else {
            float* C = (float*)Cv;
#pragma unroll
            for (int j = 0; j < TN / 2; j += 2) {
                float a0, a1, a2, a3;
                unpack2(acc[i][j], a0, a1);
                unpack2(acc[i][j + 1], a2, a3);
                *(float4*)(C + (size_t)gr * N + tCol * TN + 2 * j) =
                    make_float4(a0, a1, a2, a3);
            }
        }
    }
}

// ---------------- SpMM1: fp16 gather of h1, fp32 accumulate, relu+bias -------
// (R12 configuration: 1 row/warp, uint2 loads — measured best)
__global__ void k_spmm1(const float* __restrict__ b1, int n) {
    const int gw   = blockIdx.x * (blockDim.x / 32) + (threadIdx.x >> 5);
    const int lane = threadIdx.x & 31;
    const int row  = gw;
    if (row >= n) return;

    const uint2* Hp = (const uint2*)g_h1h;   // 128 halves/row = 32 uint2
    const int s = g_off[row];
    const int e = g_off[row + 1];
    float4 acc0 = make_float4(0.f, 0.f, 0.f, 0.f);
    float4 acc1 = make_float4(0.f, 0.f, 0.f, 0.f);
    int p = s;
    for (; p + 2 <= e; p += 2) {
        int2  e0 = g_csre[p];
        int2  e1 = g_csre[p + 1];
        float n0 = __int_as_float(e0.y);
        float n1 = __int_as_float(e1.y);
        uint2 v0 = Hp[(size_t)e0.x * 32 + lane];
        uint2 v1 = Hp[(size_t)e1.x * 32 + lane];
        float2 f00 = __half22float2(*(__half2*)&v0.x);
        float2 f01 = __half22float2(*(__half2*)&v0.y);
        float2 f10 = __half22float2(*(__half2*)&v1.x);
        float2 f11 = __half22float2(*(__half2*)&v1.y);
        acc0.x = fmaf(n0, f00.x, acc0.x); acc1.x = fmaf(n1, f10.x, acc1.x);
        acc0.y = fmaf(n0, f00.y, acc0.y); acc1.y = fmaf(n1, f10.y, acc1.y);
        acc0.z = fmaf(n0, f01.x, acc0.z); acc1.z = fmaf(n1, f11.x, acc1.z);
        acc0.w = fmaf(n0, f01.y, acc0.w); acc1.w = fmaf(n1, f11.y, acc1.w);
    }
    if (p < e) {
        int2  e0 = g_csre[p];
        float n0 = __int_as_float(e0.y);
        uint2 v0 = Hp[(size_t)e0.x * 32 + lane];
        float2 f00 = __half22float2(*(__half2*)&v0.x);
        float2 f01 = __half22float2(*(__half2*)&v0.y);
        acc0.x = fmaf(n0, f00.x, acc0.x);
        acc0.y = fmaf(n0, f00.y, acc0.y);
        acc0.z = fmaf(n0, f01.x, acc0.z);
        acc0.w = fmaf(n0, f01.y, acc0.w);
    }
    float4 b = *(const float4*)(b1 + lane * 4);
    acc0.x = fmaxf(acc0.x + acc1.x + b.x, 0.f);
    acc0.y = fmaxf(acc0.y + acc1.y + b.y, 0.f);
    acc0.z = fmaxf(acc0.z + acc1.z + b.z, 0.f);
    acc0.w = fmaxf(acc0.w + acc1.w + b.w, 0.f);
    *(float4*)(g_hr + (size_t)row * NH + lane * 4) = acc0;
}

// ---------------- SpMM2: fp16 gather of h2 (2 rows per warp) ------------------
__global__ void k_spmm2(const float* __restrict__ b2, float* __restrict__ out, int n) {
    const int gw   = blockIdx.x * (blockDim.x / 32) + (threadIdx.x >> 5);
    const int lane = threadIdx.x & 31;
    const int sub  = lane >> 4;          // 2 rows per warp
    const int li   = lane & 15;          // 16 lanes x 4 cols = 64 cols
    const int row  = gw * 2 + sub;
    if (row >= n) return;

    const uint2* Hp = (const uint2*)g_h2h;   // 64 halves/row = 16 uint2
    const int s = g_off[row];
    const int e = g_off[row + 1];
    float4 acc0 = make_float4(0.f, 0.f, 0.f, 0.f);
    float4 acc1 = make_float4(0.f, 0.f, 0.f, 0.f);
    int p = s;
    for (; p + 2 <= e; p += 2) {
        int2  e0 = g_csre[p];
        int2  e1 = g_csre[p + 1];
        float n0 = __int_as_float(e0.y);
        float n1 = __int_as_float(e1.y);
        uint2 v0 = Hp[(size_t)e0.x * 16 + li];
        uint2 v1 = Hp[(size_t)e1.x * 16 + li];
        float2 f00 = __half22float2(*(__half2*)&v0.x);
        float2 f01 = __half22float2(*(__half2*)&v0.y);
        float2 f10 = __half22float2(*(__half2*)&v1.x);
        float2 f11 = __half22float2(*(__half2*)&v1.y);
        acc0.x = fmaf(n0, f00.x, acc0.x); acc1.x = fmaf(n1, f10.x, acc1.x);
        acc0.y = fmaf(n0, f00.y, acc0.y); acc1.y = fmaf(n1, f10.y, acc1.y);
        acc0.z = fmaf(n0, f01.x, acc0.z); acc1.z = fmaf(n1, f11.x, acc1.z);
        acc0.w = fmaf(n0, f01.y, acc0.w); acc1.w = fmaf(n1, f11.y, acc1.w);
    }
    if (p < e) {
        int2  e0 = g_csre[p];
        float n0 = __int_as_float(e0.y);
        uint2 v0 = Hp[(size_t)e0.x * 16 + li];
        float2 f00 = __half22float2(*(__half2*)&v0.x);
        float2 f01 = __half22float2(*(__half2*)&v0.y);
        acc0.x = fmaf(n0, f00.x, acc0.x);
        acc0.y = fmaf(n0, f00.y, acc0.y);
        acc0.z = fmaf(n0, f01.x, acc0.z);
        acc0.w = fmaf(n0, f01.y, acc0.w);
    }
    float4 b = *(const float4*)(b2 + li * 4);
    acc0.x += acc1.x + b.x;
    acc0.y += acc1.y + b.y;
    acc0.z += acc1.z + b.z;
    acc0.w += acc1.w + b.w;
    *(float4*)(out + (size_t)row * NO + li * 4) = acc0;
}

// ---------------- thin wrappers binding __device__ globals ----------------
// GEMM1: BM=64 (782 CTAs, 128 thr), plain A smem, fp16 out.
__global__ void __launch_bounds__(128) k_gemm1(const float* __restrict__ x,
                                               const float* __restrict__ W1, int n) {
    gemm_body<64, 128, 16, 8, 8, true>(x, W1, g_h1h, n, NH, NF);
}
// GEMM2: BK=32, plain A smem, fp16 out.
__global__ void __launch_bounds__(128) k_gemm2(const float* __restrict__ W2, int n) {
    gemm_body<128, 64, 32, 8, 8, true>(g_hr, W2, g_h2h, n, NO, NH);
}

// ---------------- launcher ----------------
extern "C" void kernel_launch(void* const* d_in, const int* in_sizes, int n_in,
                              void* d_out, int out_size) {
    const float* x  = (const float*)d_in[0];
    const int*   ei = (const int*)d_in[1];     // int32 edge_index [2, E]
    const float* W1 = (const float*)d_in[2];
    const float* b1 = (const float*)d_in[3];
    const float* W2 = (const float*)d_in[4];
    const float* b2 = (const float*)d_in[5];
    float* out = (float*)d_out;

    const int n = in_sizes[0] / NF;   // 50000
    const int E = in_sizes[1] / 2;    // 800000
    const int nb = (n + 255) / 256;

    // Lazily-created side stream + events (host objects only; created once).
    static cudaStream_t s2 = nullptr;
    static cudaEvent_t evRoot = nullptr, evG = nullptr;
    static bool tried = false;
    if (!tried) {
        tried = true;
        bool ok = (cudaStreamCreateWithFlags(&s2, cudaStreamNonBlocking) == cudaSuccess);
        ok = ok && (cudaEventCreateWithFlags(&evRoot, cudaEventDisableTiming) == cudaSuccess);
        ok = ok && (cudaEventCreateWithFlags(&evG,    cudaEventDisableTiming) == cudaSuccess);
        if (!ok) s2 = nullptr;
    }
    const bool fork = (s2 != nullptr);
    cudaStream_t sg = fork ? s2 : (cudaStream_t)0;

    // Fork point recorded BEFORE any prep launch: gemm1 depends only on evRoot,
    // so it runs parallel with the prep chain regardless of API call order.
    if (fork) {
        cudaEventRecord(evRoot, 0);
        cudaStreamWaitEvent(s2, evRoot, 0);
    }

    // ---- graph prep (part 1) on main stream ----
    k_zero_deg<<<(n + 255) / 256, 256>>>();                 // launch idx 0
    k_hist<<<(E + 255) / 256, 256>>>(ei, E, n);             // idx 1
    k_blocksum<<<nb, 256>>>(n);                             // idx 2

    // ---- GEMM1 as the 4th kernel launch (idx 3) so ncu's capture window
    //      lands on it; dependency-wise still parallel with all prep. ----
    k_gemm1<<<(n + 63) / 64, 128, 0, sg>>>(x, W1, n);       // idx 3
    if (fork) cudaEventRecord(evG, s2);

    // ---- graph prep (part 2) on main stream ----
    k_scan_bases<<<1, 256>>>(nb);                           // idx 4
    k_offsets<<<nb, 256>>>(n);                              // idx 5
    k_fill<<<(E + 255) / 256, 256>>>(ei, E, n);             // idx 6

    // ---- join: SpMM1 needs both h1 and the CSR ----
    if (fork) cudaStreamWaitEvent(0, evG, 0);
    k_spmm1<<<(n + 7) / 8, 256>>>(b1, n);
    // layer 2: h2 = hr @ W2 ; out = Ahat @ h2 + b2
    k_gemm2<<<(n + 127) / 128, 128>>>(W2, n);
    k_spmm2<<<(n / 2 + 7) / 8, 256>>>(b2, out, n);
}

// round 15
// speedup vs baseline: 1.0289x; 1.0266x over previous
#include <cuda_runtime.h>
#include <cuda_fp16.h>
#include <cstdint>

// Problem constants (fixed by the dataset)
#define NN   50000
#define EE   800000
#define NF   256
#define NH   128
#define NO   64
#define NB   ((NN + 255) / 256)   // 196 scan blocks

// ---------------- scratch (no allocations allowed) ----------------
__device__ int    g_deg[NN];
__device__ int    g_cursor[NN];
__device__ float  g_dis[NN];
__device__ int    g_off[NN + 1];
__device__ int    g_bsum[NB];
__device__ int    g_bbase[NB];
__device__ int2   g_csre[EE];               // (src, norm-bits) packed
__device__ __half g_h1h[(size_t)NN * NH];   // x @ W1 (fp16 storage)
__device__ float  g_hr[(size_t)NN * NH];    // relu(agg1 + b1)
__device__ __half g_h2h[(size_t)NN * NO];   // hr @ W2 (fp16 storage)

// ---------------- packed f32x2 helpers ----------------
__device__ __forceinline__ unsigned long long pack2(float lo, float hi) {
    unsigned long long r;
    asm("mov.b64 %0, {%1, %2};" : "=l"(r) : "f"(lo), "f"(hi));
    return r;
}
__device__ __forceinline__ void unpack2(unsigned long long v, float& lo, float& hi) {
    asm("mov.b64 {%0, %1}, %2;" : "=f"(lo), "=f"(hi) : "l"(v));
}
__device__ __forceinline__ unsigned long long fma2(unsigned long long a,
                                                   unsigned long long b,
                                                   unsigned long long c) {
    unsigned long long d;
    asm("fma.rn.f32x2 %0, %1, %2, %3;" : "=l"(d) : "l"(a), "l"(b), "l"(c));
    return d;
}

// ---------------- small graph-prep kernels ----------------
__global__ void k_zero_deg() {
    int i = blockIdx.x * blockDim.x + threadIdx.x;
    if (i < NN) g_deg[i] = 0;
}

// edge_index is int32
__global__ void k_hist(const int* __restrict__ ei, int E, int n) {
    int e = blockIdx.x * blockDim.x + threadIdx.x;
    if (e < E) {
        int d = ei[E + e];
        if ((unsigned)d < (unsigned)n) atomicAdd(&g_deg[d], 1);
    }
}

__global__ void k_blocksum(int n) {
    __shared__ int sh[256];
    int i = blockIdx.x * 256 + threadIdx.x;
    sh[threadIdx.x] = (i < n) ? g_deg[i] : 0;
    __syncthreads();
    for (int s = 128; s > 0; s >>= 1) {
        if (threadIdx.x < s) sh[threadIdx.x] += sh[threadIdx.x + s];
        __syncthreads();
    }
    if (threadIdx.x == 0) g_bsum[blockIdx.x] = sh[0];
}

// parallel exclusive scan of block sums (nb <= 256), single block
__global__ void k_scan_bases(int nb) {
    __shared__ int sh[256];
    int t = threadIdx.x;
    int v = (t < nb) ? g_bsum[t] : 0;
    sh[t] = v;
    __syncthreads();
    for (int o = 1; o < 256; o <<= 1) {
        int u = (t >= o) ? sh[t - o] : 0;
        __syncthreads();
        sh[t] += u;
        __syncthreads();
    }
    if (t < nb) g_bbase[t] = sh[t] - v;   // exclusive
}

__global__ void k_offsets(int n) {
    __shared__ int sh[256];
    int tid = threadIdx.x;
    int i = blockIdx.x * 256 + tid;
    int v = (i < n) ? g_deg[i] : 0;
    sh[tid] = v;
    __syncthreads();
    for (int ofs = 1; ofs < 256; ofs <<= 1) {
        int t = (tid >= ofs) ? sh[tid - ofs] : 0;
        __syncthreads();
        sh[tid] += t;
        __syncthreads();
    }
    if (i < n) {
        int base = g_bbase[blockIdx.x];
        g_off[i] = base + sh[tid] - v;
        g_dis[i] = (v > 0) ? rsqrtf((float)v) : 0.0f;
        g_cursor[i] = 0;
        if (i == n - 1) g_off[n] = base + sh[tid];
    }
}

__global__ void k_fill(const int* __restrict__ ei, int E, int n) {
    int e = blockIdx.x * blockDim.x + threadIdx.x;
    if (e < E) {
        int s = ei[e];
        int d = ei[E + e];
        if ((unsigned)s < (unsigned)n && (unsigned)d < (unsigned)n) {
            int pos = g_off[d] + atomicAdd(&g_cursor[d], 1);
            float nm = g_dis[s] * g_dis[d];
            g_csre[pos] = make_int2(s, __float_as_int(nm));
        }
    }
}

// ---------------- double-buffered register-tiled SGEMM (fma.f32x2) -------------
// C[M,N] = A[M,K] @ B[K,N], row-major, K % BK == 0, N == BN.
// Single __syncthreads per k-slab (compute(cur) then sts(nxt) touch disjoint
// buffers; previous barrier ordered the handoff).
// HALF_OUT: C is __half* (row stride N halves); otherwise float*.
template <int BM, int BN, int BK, int TM, int TN, bool HALF_OUT>
__device__ __forceinline__ void gemm_body(const float* __restrict__ A,
                                          const float* __restrict__ B,
                                          void* __restrict__ Cv,
                                          int M, int N, int K) {
    constexpr int NTH = (BM / TM) * (BN / TN);
    constexpr int LA = BM * BK / (4 * NTH);
    constexpr int LB = BK * BN / (4 * NTH);
    __shared__ __align__(16) float As[2][BK][BM];   // transposed
    __shared__ __align__(16) float Bs[2][BK][BN];

    const int tid = threadIdx.x;
    const int blockRow = blockIdx.x;
    const int tCol = tid % (BN / TN);
    const int tRow = tid / (BN / TN);

    float4 ra[LA], rb[LB];

    auto ldg_tile = [&](int k0) {
#pragma unroll
        for (int t = 0; t < LA; t++) {
            int i = tid + t * NTH;
            int r = i / (BK / 4);
            int kv = i % (BK / 4);
            int gr = blockRow * BM + r;
            ra[t] = (gr < M) ? *(const float4*)(A + (size_t)gr * K + k0 + kv * 4)
                             : make_float4(0.f, 0.f, 0.f, 0.f);
        }
#pragma unroll
        for (int t = 0; t < LB; t++) {
            int i = tid + t * NTH;
            int r = i / (BN / 4);
            int cv = i % (BN / 4);
            rb[t] = *(const float4*)(B + (size_t)(k0 + r) * N + cv * 4);
        }
    };
    auto sts_tile = [&](int buf) {
#pragma unroll
        for (int t = 0; t < LA; t++) {
            int i = tid + t * NTH;
            int r = i / (BK / 4);
            int kv = i % (BK / 4);
            As[buf][kv * 4 + 0][r] = ra[t].x;
            As[buf][kv * 4 + 1][r] = ra[t].y;
            As[buf][kv * 4 + 2][r] = ra[t].z;
            As[buf][kv * 4 + 3][r] = ra[t].w;
        }
#pragma unroll
        for (int t = 0; t < LB; t++) {
            int i = tid + t * NTH;
            int r = i / (BN / 4);
            int cv = i % (BN / 4);
            *(float4*)&Bs[buf][r][cv * 4] = rb[t];
        }
    };

    unsigned long long acc[TM][TN / 2];
#pragma unroll
    for (int i = 0; i < TM; i++)
#pragma unroll
        for (int j = 0; j < TN / 2; j++) acc[i][j] = 0ull;

    const int nk = K / BK;
    ldg_tile(0);
    sts_tile(0);
    __syncthreads();

    for (int kb = 0; kb < nk; kb++) {
        const int cur = kb & 1;
        if (kb + 1 < nk) ldg_tile((kb + 1) * BK);

#pragma unroll
        for (int kk = 0; kk < BK; kk++) {
            float4 a0 = *(const float4*)&As[cur][kk][tRow * TM];
            float4 a1 = *(const float4*)&As[cur][kk][tRow * TM + 4];
            unsigned long long m2[TM];
            m2[0] = pack2(a0.x, a0.x); m2[1] = pack2(a0.y, a0.y);
            m2[2] = pack2(a0.z, a0.z); m2[3] = pack2(a0.w, a0.w);
            m2[4] = pack2(a1.x, a1.x); m2[5] = pack2(a1.y, a1.y);
            m2[6] = pack2(a1.z, a1.z); m2[7] = pack2(a1.w, a1.w);
            // B row: 8 consecutive floats = 2x LDS.128
            unsigned long long b2r[TN / 2];
            const ulonglong2* bp =
                (const ulonglong2*)&Bs[cur][kk][tCol * TN];
            ulonglong2 q0 = bp[0];
            ulonglong2 q1 = bp[1];
            b2r[0] = q0.x; b2r[1] = q0.y; b2r[2] = q1.x; b2r[3] = q1.y;
#pragma unroll
            for (int i = 0; i < TM; i++)
#pragma unroll
                for (int j = 0; j < TN / 2; j++)
                    acc[i][j] = fma2(m2[i], b2r[j], acc[i][j]);
        }

        if (kb + 1 < nk) {
            sts_tile(cur ^ 1);      // disjoint buffer from the one just read
            __syncthreads();        // single barrier per slab
        }
    }

#pragma unroll
    for (int i = 0; i < TM; i++) {
        int gr = blockRow * BM + tRow * TM + i;
        if (gr >= M) continue;
        if (HALF_OUT) {
            __half* Ch = (__half*)Cv;
            uint4 pk;
            float a0, a1, a2, a3, a4, a5, a6, a7;
            unpack2(acc[i][0], a0, a1);
            unpack2(acc[i][1], a2, a3);
            unpack2(acc[i][2], a4, a5);
            unpack2(acc[i][3], a6, a7);
            __half2 p0 = __floats2half2_rn(a0, a1);
            __half2 p1 = __floats2half2_rn(a2, a3);
            __half2 p2 = __floats2half2_rn(a4, a5);
            __half2 p3 = __floats2half2_rn(a6, a7);
            pk.x = *(uint32_t*)&p0; pk.y = *(uint32_t*)&p1;
            pk.z = *(uint32_t*)&p2; pk.w = *(uint32_t*)&p3;
            *(uint4*)(Ch + (size_t)gr * N + tCol * TN) = pk;
        } else {
            float* C = (float*)Cv;
#pragma unroll
            for (int j = 0; j < TN / 2; j += 2) {
                float a0, a1, a2, a3;
                unpack2(acc[i][j], a0, a1);
                unpack2(acc[i][j + 1], a2, a3);
                *(float4*)(C + (size_t)gr * N + tCol * TN + 2 * j) =
                    make_float4(a0, a1, a2, a3);
            }
        }
    }
}

// ---------------- SpMM1: fp16 gather of h1, fp32 accumulate, relu+bias -------
// (R12 configuration: 1 row/warp, uint2 loads — measured best)
__global__ void k_spmm1(const float* __restrict__ b1, int n) {
    const int gw   = blockIdx.x * (blockDim.x / 32) + (threadIdx.x >> 5);
    const int lane = threadIdx.x & 31;
    const int row  = gw;
    if (row >= n) return;

    const uint2* Hp = (const uint2*)g_h1h;   // 128 halves/row = 32 uint2
    const int s = g_off[row];
    const int e = g_off[row + 1];
    float4 acc0 = make_float4(0.f, 0.f, 0.f, 0.f);
    float4 acc1 = make_float4(0.f, 0.f, 0.f, 0.f);
    int p = s;
    for (; p + 2 <= e; p += 2) {
        int2  e0 = g_csre[p];
        int2  e1 = g_csre[p + 1];
        float n0 = __int_as_float(e0.y);
        float n1 = __int_as_float(e1.y);
        uint2 v0 = Hp[(size_t)e0.x * 32 + lane];
        uint2 v1 = Hp[(size_t)e1.x * 32 + lane];
        float2 f00 = __half22float2(*(__half2*)&v0.x);
        float2 f01 = __half22float2(*(__half2*)&v0.y);
        float2 f10 = __half22float2(*(__half2*)&v1.x);
        float2 f11 = __half22float2(*(__half2*)&v1.y);
        acc0.x = fmaf(n0, f00.x, acc0.x); acc1.x = fmaf(n1, f10.x, acc1.x);
        acc0.y = fmaf(n0, f00.y, acc0.y); acc1.y = fmaf(n1, f10.y, acc1.y);
        acc0.z = fmaf(n0, f01.x, acc0.z); acc1.z = fmaf(n1, f11.x, acc1.z);
        acc0.w = fmaf(n0, f01.y, acc0.w); acc1.w = fmaf(n1, f11.y, acc1.w);
    }
    if (p < e) {
        int2  e0 = g_csre[p];
        float n0 = __int_as_float(e0.y);
        uint2 v0 = Hp[(size_t)e0.x * 32 + lane];
        float2 f00 = __half22float2(*(__half2*)&v0.x);
        float2 f01 = __half22float2(*(__half2*)&v0.y);
        acc0.x = fmaf(n0, f00.x, acc0.x);
        acc0.y = fmaf(n0, f00.y, acc0.y);
        acc0.z = fmaf(n0, f01.x, acc0.z);
        acc0.w = fmaf(n0, f01.y, acc0.w);
    }
    float4 b = *(const float4*)(b1 + lane * 4);
    acc0.x = fmaxf(acc0.x + acc1.x + b.x, 0.f);
    acc0.y = fmaxf(acc0.y + acc1.y + b.y, 0.f);
    acc0.z = fmaxf(acc0.z + acc1.z + b.z, 0.f);
    acc0.w = fmaxf(acc0.w + acc1.w + b.w, 0.f);
    *(float4*)(g_hr + (size_t)row * NH + lane * 4) = acc0;
}

// ---------------- SpMM2: fp16 gather of h2 (2 rows per warp) ------------------
__global__ void k_spmm2(const float* __restrict__ b2, float* __restrict__ out, int n) {
    const int gw   = blockIdx.x * (blockDim.x / 32) + (threadIdx.x >> 5);
    const int lane = threadIdx.x & 31;
    const int sub  = lane >> 4;          // 2 rows per warp
    const int li   = lane & 15;          // 16 lanes x 4 cols = 64 cols
    const int row  = gw * 2 + sub;
    if (row >= n) return;

    const uint2* Hp = (const uint2*)g_h2h;   // 64 halves/row = 16 uint2
    const int s = g_off[row];
    const int e = g_off[row + 1];
    float4 acc0 = make_float4(0.f, 0.f, 0.f, 0.f);
    float4 acc1 = make_float4(0.f, 0.f, 0.f, 0.f);
    int p = s;
    for (; p + 2 <= e; p += 2) {
        int2  e0 = g_csre[p];
        int2  e1 = g_csre[p + 1];
        float n0 = __int_as_float(e0.y);
        float n1 = __int_as_float(e1.y);
        uint2 v0 = Hp[(size_t)e0.x * 16 + li];
        uint2 v1 = Hp[(size_t)e1.x * 16 + li];
        float2 f00 = __half22float2(*(__half2*)&v0.x);
        float2 f01 = __half22float2(*(__half2*)&v0.y);
        float2 f10 = __half22float2(*(__half2*)&v1.x);
        float2 f11 = __half22float2(*(__half2*)&v1.y);
        acc0.x = fmaf(n0, f00.x, acc0.x); acc1.x = fmaf(n1, f10.x, acc1.x);
        acc0.y = fmaf(n0, f00.y, acc0.y); acc1.y = fmaf(n1, f10.y, acc1.y);
        acc0.z = fmaf(n0, f01.x, acc0.z); acc1.z = fmaf(n1, f11.x, acc1.z);
        acc0.w = fmaf(n0, f01.y, acc0.w); acc1.w = fmaf(n1, f11.y, acc1.w);
    }
    if (p < e) {
        int2  e0 = g_csre[p];
        float n0 = __int_as_float(e0.y);
        uint2 v0 = Hp[(size_t)e0.x * 16 + li];
        float2 f00 = __half22float2(*(__half2*)&v0.x);
        float2 f01 = __half22float2(*(__half2*)&v0.y);
        acc0.x = fmaf(n0, f00.x, acc0.x);
        acc0.y = fmaf(n0, f00.y, acc0.y);
        acc0.z = fmaf(n0, f01.x, acc0.z);
        acc0.w = fmaf(n0, f01.y, acc0.w);
    }
    float4 b = *(const float4*)(b2 + li * 4);
    acc0.x += acc1.x + b.x;
    acc0.y += acc1.y + b.y;
    acc0.z += acc1.z + b.z;
    acc0.w += acc1.w + b.w;
    *(float4*)(out + (size_t)row * NO + li * 4) = acc0;
}

// ---------------- thin wrappers binding __device__ globals ----------------
// GEMM1: BM=64 (782 CTAs, 128 thr), plain A smem, fp16 out.
__global__ void __launch_bounds__(128) k_gemm1(const float* __restrict__ x,
                                               const float* __restrict__ W1, int n) {
    gemm_body<64, 128, 16, 8, 8, true>(x, W1, g_h1h, n, NH, NF);
}
// GEMM2: BK=32, plain A smem, fp16 out.
__global__ void __launch_bounds__(128) k_gemm2(const float* __restrict__ W2, int n) {
    gemm_body<128, 64, 32, 8, 8, true>(g_hr, W2, g_h2h, n, NO, NH);
}

// ---------------- launcher ----------------
extern "C" void kernel_launch(void* const* d_in, const int* in_sizes, int n_in,
                              void* d_out, int out_size) {
    const float* x  = (const float*)d_in[0];
    const int*   ei = (const int*)d_in[1];     // int32 edge_index [2, E]
    const float* W1 = (const float*)d_in[2];
    const float* b1 = (const float*)d_in[3];
    const float* W2 = (const float*)d_in[4];
    const float* b2 = (const float*)d_in[5];
    float* out = (float*)d_out;

    const int n = in_sizes[0] / NF;   // 50000
    const int E = in_sizes[1] / 2;    // 800000
    const int nb = (n + 255) / 256;

    // Lazily-created side stream + events (host objects only; created once).
    static cudaStream_t s2 = nullptr;
    static cudaEvent_t evRoot = nullptr, evG = nullptr;
    static bool tried = false;
    if (!tried) {
        tried = true;
        bool ok = (cudaStreamCreateWithFlags(&s2, cudaStreamNonBlocking) == cudaSuccess);
        ok = ok && (cudaEventCreateWithFlags(&evRoot, cudaEventDisableTiming) == cudaSuccess);
        ok = ok && (cudaEventCreateWithFlags(&evG,    cudaEventDisableTiming) == cudaSuccess);
        if (!ok) s2 = nullptr;
    }
    const bool fork = (s2 != nullptr);
    cudaStream_t sg = fork ? s2 : (cudaStream_t)0;

    // ---- fork: GEMM1 FIRST (critical path) on side stream ----
    if (fork) {
        cudaEventRecord(evRoot, 0);
        cudaStreamWaitEvent(s2, evRoot, 0);
    }
    k_gemm1<<<(n + 63) / 64, 128, 0, sg>>>(x, W1, n);
    if (fork) cudaEventRecord(evG, s2);

    // ---- graph prep on main stream (overlaps with GEMM1) ----
    k_zero_deg<<<(n + 255) / 256, 256>>>();
    k_hist<<<(E + 255) / 256, 256>>>(ei, E, n);
    k_blocksum<<<nb, 256>>>(n);
    k_scan_bases<<<1, 256>>>(nb);
    k_offsets<<<nb, 256>>>(n);
    k_fill<<<(E + 255) / 256, 256>>>(ei, E, n);

    // ---- join: SpMM1 needs both h1 and the CSR ----
    if (fork) cudaStreamWaitEvent(0, evG, 0);
    k_spmm1<<<(n + 7) / 8, 256>>>(b1, n);
    // layer 2: h2 = hr @ W2 ; out = Ahat @ h2 + b2
    k_gemm2<<<(n + 127) / 128, 128>>>(W2, n);
    k_spmm2<<<(n / 2 + 7) / 8, 256>>>(b2, out, n);
}

// round 16
// speedup vs baseline: 1.1602x; 1.1275x over previous
#include <cuda_runtime.h>
#include <cuda_fp16.h>
#include <cstdint>

// Problem constants (fixed by the dataset)
#define NN   50000
#define EE   800000
#define NF   256
#define NH   128
#define NO   64
#define NB   ((NN + 255) / 256)   // 196 scan blocks

// GEMM1-MMA tiling
#define BM1  64
#define KC1  16
#define PAD  24   // padded smem row stride (halves) -> conflict-free frags

// ---------------- scratch (no allocations allowed) ----------------
__device__ int    g_deg[NN];
__device__ int    g_cursor[NN];
__device__ float  g_dis[NN];
__device__ int    g_off[NN + 1];
__device__ int    g_bsum[NB];
__device__ int    g_bbase[NB];
__device__ int2   g_csre[EE];               // (src, norm-bits) packed
__device__ __half g_h1h[(size_t)NN * NH];   // x @ W1 (fp16 storage)
__device__ float  g_hr[(size_t)NN * NH];    // relu(agg1 + b1)
__device__ __half g_h2h[(size_t)NN * NO];   // hr @ W2 (fp16 storage)
__device__ __half g_w1h[NH * NF];           // W1^T hi  [N=128][K=256]
__device__ __half g_w1l[NH * NF];           // W1^T lo

// ---------------- packed f32x2 helpers (FFMA gemm2) ----------------
__device__ __forceinline__ unsigned long long pack2(float lo, float hi) {
    unsigned long long r;
    asm("mov.b64 %0, {%1, %2};" : "=l"(r) : "f"(lo), "f"(hi));
    return r;
}
__device__ __forceinline__ void unpack2(unsigned long long v, float& lo, float& hi) {
    asm("mov.b64 {%0, %1}, %2;" : "=f"(lo), "=f"(hi) : "l"(v));
}
__device__ __forceinline__ unsigned long long fma2(unsigned long long a,
                                                   unsigned long long b,
                                                   unsigned long long c) {
    unsigned long long d;
    asm("fma.rn.f32x2 %0, %1, %2, %3;" : "=l"(d) : "l"(a), "l"(b), "l"(c));
    return d;
}

// ---------------- small graph-prep kernels ----------------
__global__ void k_zero_deg() {
    int i = blockIdx.x * blockDim.x + threadIdx.x;
    if (i < NN) g_deg[i] = 0;
}

__global__ void k_hist(const int* __restrict__ ei, int E, int n) {
    int e = blockIdx.x * blockDim.x + threadIdx.x;
    if (e < E) {
        int d = ei[E + e];
        if ((unsigned)d < (unsigned)n) atomicAdd(&g_deg[d], 1);
    }
}

__global__ void k_blocksum(int n) {
    __shared__ int sh[256];
    int i = blockIdx.x * 256 + threadIdx.x;
    sh[threadIdx.x] = (i < n) ? g_deg[i] : 0;
    __syncthreads();
    for (int s = 128; s > 0; s >>= 1) {
        if (threadIdx.x < s) sh[threadIdx.x] += sh[threadIdx.x + s];
        __syncthreads();
    }
    if (threadIdx.x == 0) g_bsum[blockIdx.x] = sh[0];
}

__global__ void k_scan_bases(int nb) {
    __shared__ int sh[256];
    int t = threadIdx.x;
    int v = (t < nb) ? g_bsum[t] : 0;
    sh[t] = v;
    __syncthreads();
    for (int o = 1; o < 256; o <<= 1) {
        int u = (t >= o) ? sh[t - o] : 0;
        __syncthreads();
        sh[t] += u;
        __syncthreads();
    }
    if (t < nb) g_bbase[t] = sh[t] - v;   // exclusive
}

__global__ void k_offsets(int n) {
    __shared__ int sh[256];
    int tid = threadIdx.x;
    int i = blockIdx.x * 256 + tid;
    int v = (i < n) ? g_deg[i] : 0;
    sh[tid] = v;
    __syncthreads();
    for (int ofs = 1; ofs < 256; ofs <<= 1) {
        int t = (tid >= ofs) ? sh[tid - ofs] : 0;
        __syncthreads();
        sh[tid] += t;
        __syncthreads();
    }
    if (i < n) {
        int base = g_bbase[blockIdx.x];
        g_off[i] = base + sh[tid] - v;
        g_dis[i] = (v > 0) ? rsqrtf((float)v) : 0.0f;
        g_cursor[i] = 0;
        if (i == n - 1) g_off[n] = base + sh[tid];
    }
}

__global__ void k_fill(const int* __restrict__ ei, int E, int n) {
    int e = blockIdx.x * blockDim.x + threadIdx.x;
    if (e < E) {
        int s = ei[e];
        int d = ei[E + e];
        if ((unsigned)s < (unsigned)n && (unsigned)d < (unsigned)n) {
            int pos = g_off[d] + atomicAdd(&g_cursor[d], 1);
            float nm = g_dis[s] * g_dis[d];
            g_csre[pos] = make_int2(s, __float_as_int(nm));
        }
    }
}

// ---------------- W1 transpose + fp16 hi/lo split ----------------
__global__ void k_wprep(const float* __restrict__ W1) {
    int i = blockIdx.x * 256 + threadIdx.x;
    if (i < NH * NF) {
        int nr = i / NF, k = i % NF;
        float w = W1[(size_t)k * NH + nr];
        __half h = __float2half_rn(w);
        g_w1h[i] = h;
        g_w1l[i] = __float2half_rn(w - __half2float(h));
    }
}

// ---------------- GEMM1 via mma.sync (HMMA), fp16 split, fp32 acc ------------
__device__ __forceinline__ void mma16816(float* c, const uint32_t* a,
                                         const uint32_t* b) {
    asm volatile(
        "mma.sync.aligned.m16n8k16.row.col.f32.f16.f16.f32 "
        "{%0,%1,%2,%3}, {%4,%5,%6,%7}, {%8,%9}, {%0,%1,%2,%3};"
        : "+f"(c[0]), "+f"(c[1]), "+f"(c[2]), "+f"(c[3])
        : "r"(a[0]), "r"(a[1]), "r"(a[2]), "r"(a[3]), "r"(b[0]), "r"(b[1]));
}

__global__ void __launch_bounds__(256) k_gemm1_mma(const float* __restrict__ x, int M) {
    __shared__ __half sAh[2][BM1][PAD];
    __shared__ __half sAl[2][BM1][PAD];
    __shared__ __half sBh[2][NH][PAD];
    __shared__ __half sBl[2][NH][PAD];

    const int tid  = threadIdx.x;
    const int lane = tid & 31, wid = tid >> 5;
    const int wr = wid & 3, wc = wid >> 2;       // 4 x 2 warp grid
    const int row0 = blockIdx.x * BM1;

    // staging indices
    const int ar = tid >> 2, ac = (tid & 3) * 4;  // A: row, col (floats)
    const int bn = tid >> 1, bo = (tid & 1) * 8;  // B: n-row, k-offset (halves)

    float4 ra; uint4 rbh, rbl;
    auto ldg = [&](int kc) {
        int k0 = kc * KC1;
        int gr = row0 + ar;
        ra = (gr < M) ? *(const float4*)(x + (size_t)gr * NF + k0 + ac)
                      : make_float4(0.f, 0.f, 0.f, 0.f);
        rbh = *(const uint4*)(g_w1h + (size_t)bn * NF + k0 + bo);
        rbl = *(const uint4*)(g_w1l + (size_t)bn * NF + k0 + bo);
    };
    auto sts = [&](int buf) {
        __half h0 = __float2half_rn(ra.x), h1 = __float2half_rn(ra.y);
        __half h2 = __float2half_rn(ra.z), h3 = __float2half_rn(ra.w);
        __half l0 = __float2half_rn(ra.x - __half2float(h0));
        __half l1 = __float2half_rn(ra.y - __half2float(h1));
        __half l2 = __float2half_rn(ra.z - __half2float(h2));
        __half l3 = __float2half_rn(ra.w - __half2float(h3));
        __half2 hh0 = __halves2half2(h0, h1), hh1 = __halves2half2(h2, h3);
        __half2 ll0 = __halves2half2(l0, l1), ll1 = __halves2half2(l2, l3);
        *(uint2*)&sAh[buf][ar][ac] = make_uint2(*(uint32_t*)&hh0, *(uint32_t*)&hh1);
        *(uint2*)&sAl[buf][ar][ac] = make_uint2(*(uint32_t*)&ll0, *(uint32_t*)&ll1);
        *(uint4*)&sBh[buf][bn][bo] = rbh;
        *(uint4*)&sBl[buf][bn][bo] = rbl;
    };

    float acc[8][4];
#pragma unroll
    for (int t = 0; t < 8; t++)
#pragma unroll
        for (int j = 0; j < 4; j++) acc[t][j] = 0.f;

    const int fr = lane >> 2;            // fragment row (0..7)
    const int fc = (lane & 3) * 2;       // fragment col pair

    ldg(0); sts(0); __syncthreads();

    constexpr int NKC = NF / KC1;        // 16 chunks
    for (int kc = 0; kc < NKC; kc++) {
        const int cur = kc & 1;
        if (kc + 1 < NKC) ldg(kc + 1);

        const int arow = wr * 16 + fr;
        uint32_t ah[4], al[4];
        ah[0] = *(const uint32_t*)&sAh[cur][arow][fc];
        ah[1] = *(const uint32_t*)&sAh[cur][arow + 8][fc];
        ah[2] = *(const uint32_t*)&sAh[cur][arow][fc + 8];
        ah[3] = *(const uint32_t*)&sAh[cur][arow + 8][fc + 8];
        al[0] = *(const uint32_t*)&sAl[cur][arow][fc];
        al[1] = *(const uint32_t*)&sAl[cur][arow + 8][fc];
        al[2] = *(const uint32_t*)&sAl[cur][arow][fc + 8];
        al[3] = *(const uint32_t*)&sAl[cur][arow + 8][fc + 8];

        uint32_t bh[8][2], bl[8][2];
#pragma unroll
        for (int t = 0; t < 8; t++) {
            int nrow = wc * 64 + t * 8 + fr;
            bh[t][0] = *(const uint32_t*)&sBh[cur][nrow][fc];
            bh[t][1] = *(const uint32_t*)&sBh[cur][nrow][fc + 8];
            bl[t][0] = *(const uint32_t*)&sBl[cur][nrow][fc];
            bl[t][1] = *(const uint32_t*)&sBl[cur][nrow][fc + 8];
        }

#pragma unroll
        for (int t = 0; t < 8; t++) mma16816(acc[t], ah, bh[t]);
#pragma unroll
        for (int t = 0; t < 8; t++) mma16816(acc[t], ah, bl[t]);
#pragma unroll
        for (int t = 0; t < 8; t++) mma16816(acc[t], al, bh[t]);

        if (kc + 1 < NKC) {
            sts(cur ^ 1);
            __syncthreads();
        }
    }

    // epilogue: fp16 store to g_h1h
    const int orow = row0 + wr * 16 + fr;
#pragma unroll
    for (int t = 0; t < 8; t++) {
        int col = wc * 64 + t * 8 + fc;
        if (orow < M) {
            __half2 v = __floats2half2_rn(acc[t][0], acc[t][1]);
            *(uint32_t*)(g_h1h + (size_t)orow * NH + col) = *(uint32_t*)&v;
        }
        if (orow + 8 < M) {
            __half2 v = __floats2half2_rn(acc[t][2], acc[t][3]);
            *(uint32_t*)(g_h1h + (size_t)(orow + 8) * NH + col) = *(uint32_t*)&v;
        }
    }
}

// ---------------- double-buffered register-tiled SGEMM (fma.f32x2) -------------
// (GEMM2 only now.)  C[M,N] = A[M,K] @ B[K,N]; HALF_OUT -> __half* C.
template <int BM, int BN, int BK, int TM, int TN, bool HALF_OUT>
__device__ __forceinline__ void gemm_body(const float* __restrict__ A,
                                          const float* __restrict__ B,
                                          void* __restrict__ Cv,
                                          int M, int N, int K) {
    constexpr int NTH = (BM / TM) * (BN / TN);
    constexpr int LA = BM * BK / (4 * NTH);
    constexpr int LB = BK * BN / (4 * NTH);
    __shared__ __align__(16) float As[2][BK][BM];
    __shared__ __align__(16) float Bs[2][BK][BN];

    const int tid = threadIdx.x;
    const int blockRow = blockIdx.x;
    const int tCol = tid % (BN / TN);
    const int tRow = tid / (BN / TN);

    float4 ra[LA], rb[LB];

    auto ldg_tile = [&](int k0) {
#pragma unroll
        for (int t = 0; t < LA; t++) {
            int i = tid + t * NTH;
            int r = i / (BK / 4);
            int kv = i % (BK / 4);
            int gr = blockRow * BM + r;
            ra[t] = (gr < M) ? *(const float4*)(A + (size_t)gr * K + k0 + kv * 4)
                             : make_float4(0.f, 0.f, 0.f, 0.f);
        }
#pragma unroll
        for (int t = 0; t < LB; t++) {
            int i = tid + t * NTH;
            int r = i / (BN / 4);
            int cv = i % (BN / 4);
            rb[t] = *(const float4*)(B + (size_t)(k0 + r) * N + cv * 4);
        }
    };
    auto sts_tile = [&](int buf) {
#pragma unroll
        for (int t = 0; t < LA; t++) {
            int i = tid + t * NTH;
            int r = i / (BK / 4);
            int kv = i % (BK / 4);
            As[buf][kv * 4 + 0][r] = ra[t].x;
            As[buf][kv * 4 + 1][r] = ra[t].y;
            As[buf][kv * 4 + 2][r] = ra[t].z;
            As[buf][kv * 4 + 3][r] = ra[t].w;
        }
#pragma unroll
        for (int t = 0; t < LB; t++) {
            int i = tid + t * NTH;
            int r = i / (BN / 4);
            int cv = i % (BN / 4);
            *(float4*)&Bs[buf][r][cv * 4] = rb[t];
        }
    };

    unsigned long long acc[TM][TN / 2];
#pragma unroll
    for (int i = 0; i < TM; i++)
#pragma unroll
        for (int j = 0; j < TN / 2; j++) acc[i][j] = 0ull;

    const int nk = K / BK;
    ldg_tile(0);
    sts_tile(0);
    __syncthreads();

    for (int kb = 0; kb < nk; kb++) {
        const int cur = kb & 1;
        if (kb + 1 < nk) ldg_tile((kb + 1) * BK);

#pragma unroll
        for (int kk = 0; kk < BK; kk++) {
            float4 a0 = *(const float4*)&As[cur][kk][tRow * TM];
            float4 a1 = *(const float4*)&As[cur][kk][tRow * TM + 4];
            unsigned long long m2[TM];
            m2[0] = pack2(a0.x, a0.x); m2[1] = pack2(a0.y, a0.y);
            m2[2] = pack2(a0.z, a0.z); m2[3] = pack2(a0.w, a0.w);
            m2[4] = pack2(a1.x, a1.x); m2[5] = pack2(a1.y, a1.y);
            m2[6] = pack2(a1.z, a1.z); m2[7] = pack2(a1.w, a1.w);
            unsigned long long b2r[TN / 2];
            const ulonglong2* bp = (const ulonglong2*)&Bs[cur][kk][tCol * TN];
            ulonglong2 q0 = bp[0];
            ulonglong2 q1 = bp[1];
            b2r[0] = q0.x; b2r[1] = q0.y; b2r[2] = q1.x; b2r[3] = q1.y;
#pragma unroll
            for (int i = 0; i < TM; i++)
#pragma unroll
                for (int j = 0; j < TN / 2; j++)
                    acc[i][j] = fma2(m2[i], b2r[j], acc[i][j]);
        }

        if (kb + 1 < nk) {
            sts_tile(cur ^ 1);
            __syncthreads();
        }
    }

#pragma unroll
    for (int i = 0; i < TM; i++) {
        int gr = blockRow * BM + tRow * TM + i;
        if (gr >= M) continue;
        if (HALF_OUT) {
            __half* Ch = (__half*)Cv;
            uint4 pk;
            float a0, a1, a2, a3, a4, a5, a6, a7;
            unpack2(acc[i][0], a0, a1);
            unpack2(acc[i][1], a2, a3);
            unpack2(acc[i][2], a4, a5);
            unpack2(acc[i][3], a6, a7);
            __half2 p0 = __floats2half2_rn(a0, a1);
            __half2 p1 = __floats2half2_rn(a2, a3);
            __half2 p2 = __floats2half2_rn(a4, a5);
            __half2 p3 = __floats2half2_rn(a6, a7);
            pk.x = *(uint32_t*)&p0; pk.y = *(uint32_t*)&p1;
            pk.z = *(uint32_t*)&p2; pk.w = *(uint32_t*)&p3;
            *(uint4*)(Ch + (size_t)gr * N + tCol * TN) = pk;
        } else {
            float* C = (float*)Cv;
#pragma unroll
            for (int j = 0; j < TN / 2; j += 2) {
                float a0, a1, a2, a3;
                unpack2(acc[i][j], a0, a1);
                unpack2(acc[i][j + 1], a2, a3);
                *(float4*)(C + (size_t)gr * N + tCol * TN + 2 * j) =
                    make_float4(a0, a1, a2, a3);
            }
        }
    }
}

// ---------------- SpMM1: fp16 gather of h1, fp32 accumulate, relu+bias -------
__global__ void k_spmm1(const float* __restrict__ b1, int n) {
    const int gw   = blockIdx.x * (blockDim.x / 32) + (threadIdx.x >> 5);
    const int lane = threadIdx.x & 31;
    const int row  = gw;
    if (row >= n) return;

    const uint2* Hp = (const uint2*)g_h1h;   // 128 halves/row = 32 uint2
    const int s = g_off[row];
    const int e = g_off[row + 1];
    float4 acc0 = make_float4(0.f, 0.f, 0.f, 0.f);
    float4 acc1 = make_float4(0.f, 0.f, 0.f, 0.f);
    int p = s;
    for (; p + 2 <= e; p += 2) {
        int2  e0 = g_csre[p];
        int2  e1 = g_csre[p + 1];
        float n0 = __int_as_float(e0.y);
        float n1 = __int_as_float(e1.y);
        uint2 v0 = Hp[(size_t)e0.x * 32 + lane];
        uint2 v1 = Hp[(size_t)e1.x * 32 + lane];
        float2 f00 = __half22float2(*(__half2*)&v0.x);
        float2 f01 = __half22float2(*(__half2*)&v0.y);
        float2 f10 = __half22float2(*(__half2*)&v1.x);
        float2 f11 = __half22float2(*(__half2*)&v1.y);
        acc0.x = fmaf(n0, f00.x, acc0.x); acc1.x = fmaf(n1, f10.x, acc1.x);
        acc0.y = fmaf(n0, f00.y, acc0.y); acc1.y = fmaf(n1, f10.y, acc1.y);
        acc0.z = fmaf(n0, f01.x, acc0.z); acc1.z = fmaf(n1, f11.x, acc1.z);
        acc0.w = fmaf(n0, f01.y, acc0.w); acc1.w = fmaf(n1, f11.y, acc1.w);
    }
    if (p < e) {
        int2  e0 = g_csre[p];
        float n0 = __int_as_float(e0.y);
        uint2 v0 = Hp[(size_t)e0.x * 32 + lane];
        float2 f00 = __half22float2(*(__half2*)&v0.x);
        float2 f01 = __half22float2(*(__half2*)&v0.y);
        acc0.x = fmaf(n0, f00.x, acc0.x);
        acc0.y = fmaf(n0, f00.y, acc0.y);
        acc0.z = fmaf(n0, f01.x, acc0.z);
        acc0.w = fmaf(n0, f01.y, acc0.w);
    }
    float4 b = *(const float4*)(b1 + lane * 4);
    acc0.x = fmaxf(acc0.x + acc1.x + b.x, 0.f);
    acc0.y = fmaxf(acc0.y + acc1.y + b.y, 0.f);
    acc0.z = fmaxf(acc0.z + acc1.z + b.z, 0.f);
    acc0.w = fmaxf(acc0.w + acc1.w + b.w, 0.f);
    *(float4*)(g_hr + (size_t)row * NH + lane * 4) = acc0;
}

// ---------------- SpMM2: fp16 gather of h2 (2 rows per warp) ------------------
__global__ void k_spmm2(const float* __restrict__ b2, float* __restrict__ out, int n) {
    const int gw   = blockIdx.x * (blockDim.x / 32) + (threadIdx.x >> 5);
    const int lane = threadIdx.x & 31;
    const int sub  = lane >> 4;
    const int li   = lane & 15;
    const int row  = gw * 2 + sub;
    if (row >= n) return;

    const uint2* Hp = (const uint2*)g_h2h;   // 64 halves/row = 16 uint2
    const int s = g_off[row];
    const int e = g_off[row + 1];
    float4 acc0 = make_float4(0.f, 0.f, 0.f, 0.f);
    float4 acc1 = make_float4(0.f, 0.f, 0.f, 0.f);
    int p = s;
    for (; p + 2 <= e; p += 2) {
        int2  e0 = g_csre[p];
        int2  e1 = g_csre[p + 1];
        float n0 = __int_as_float(e0.y);
        float n1 = __int_as_float(e1.y);
        uint2 v0 = Hp[(size_t)e0.x * 16 + li];
        uint2 v1 = Hp[(size_t)e1.x * 16 + li];
        float2 f00 = __half22float2(*(__half2*)&v0.x);
        float2 f01 = __half22float2(*(__half2*)&v0.y);
        float2 f10 = __half22float2(*(__half2*)&v1.x);
        float2 f11 = __half22float2(*(__half2*)&v1.y);
        acc0.x = fmaf(n0, f00.x, acc0.x); acc1.x = fmaf(n1, f10.x, acc1.x);
        acc0.y = fmaf(n0, f00.y, acc0.y); acc1.y = fmaf(n1, f10.y, acc1.y);
        acc0.z = fmaf(n0, f01.x, acc0.z); acc1.z = fmaf(n1, f11.x, acc1.z);
        acc0.w = fmaf(n0, f01.y, acc0.w); acc1.w = fmaf(n1, f11.y, acc1.w);
    }
    if (p < e) {
        int2  e0 = g_csre[p];
        float n0 = __int_as_float(e0.y);
        uint2 v0 = Hp[(size_t)e0.x * 16 + li];
        float2 f00 = __half22float2(*(__half2*)&v0.x);
        float2 f01 = __half22float2(*(__half2*)&v0.y);
        acc0.x = fmaf(n0, f00.x, acc0.x);
        acc0.y = fmaf(n0, f00.y, acc0.y);
        acc0.z = fmaf(n0, f01.x, acc0.z);
        acc0.w = fmaf(n0, f01.y, acc0.w);
    }
    float4 b = *(const float4*)(b2 + li * 4);
    acc0.x += acc1.x + b.x;
    acc0.y += acc1.y + b.y;
    acc0.z += acc1.z + b.z;
    acc0.w += acc1.w + b.w;
    *(float4*)(out + (size_t)row * NO + li * 4) = acc0;
}

// ---------------- thin wrappers binding __device__ globals ----------------
// GEMM2: BK=32, plain A smem, fp16 out (FFMA path).
__global__ void __launch_bounds__(128) k_gemm2(const float* __restrict__ W2, int n) {
    gemm_body<128, 64, 32, 8, 8, true>(g_hr, W2, g_h2h, n, NO, NH);
}

// ---------------- launcher ----------------
extern "C" void kernel_launch(void* const* d_in, const int* in_sizes, int n_in,
                              void* d_out, int out_size) {
    const float* x  = (const float*)d_in[0];
    const int*   ei = (const int*)d_in[1];     // int32 edge_index [2, E]
    const float* W1 = (const float*)d_in[2];
    const float* b1 = (const float*)d_in[3];
    const float* W2 = (const float*)d_in[4];
    const float* b2 = (const float*)d_in[5];
    float* out = (float*)d_out;

    const int n = in_sizes[0] / NF;   // 50000
    const int E = in_sizes[1] / 2;    // 800000
    const int nb = (n + 255) / 256;

    // Lazily-created side stream + events (host objects only; created once).
    static cudaStream_t s2 = nullptr;
    static cudaEvent_t evRoot = nullptr, evG = nullptr;
    static bool tried = false;
    if (!tried) {
        tried = true;
        bool ok = (cudaStreamCreateWithFlags(&s2, cudaStreamNonBlocking) == cudaSuccess);
        ok = ok && (cudaEventCreateWithFlags(&evRoot, cudaEventDisableTiming) == cudaSuccess);
        ok = ok && (cudaEventCreateWithFlags(&evG,    cudaEventDisableTiming) == cudaSuccess);
        if (!ok) s2 = nullptr;
    }
    const bool fork = (s2 != nullptr);
    cudaStream_t sg = fork ? s2 : (cudaStream_t)0;

    // ---- fork: W1 prep + GEMM1 (mma) on side stream, parallel with graph prep
    if (fork) {
        cudaEventRecord(evRoot, 0);
        cudaStreamWaitEvent(s2, evRoot, 0);
    }
    k_wprep<<<(NH * NF + 255) / 256, 256, 0, sg>>>(W1);
    k_gemm1_mma<<<(n + BM1 - 1) / BM1, 256, 0, sg>>>(x, n);
    if (fork) cudaEventRecord(evG, s2);

    // ---- graph prep on main stream (overlaps with GEMM1) ----
    k_zero_deg<<<(n + 255) / 256, 256>>>();
    k_hist<<<(E + 255) / 256, 256>>>(ei, E, n);
    k_blocksum<<<nb, 256>>>(n);
    k_scan_bases<<<1, 256>>>(nb);
    k_offsets<<<nb, 256>>>(n);
    k_fill<<<(E + 255) / 256, 256>>>(ei, E, n);

    // ---- join: SpMM1 needs both h1 and the CSR ----
    if (fork) cudaStreamWaitEvent(0, evG, 0);
    k_spmm1<<<(n + 7) / 8, 256>>>(b1, n);
    // layer 2: h2 = hr @ W2 ; out = Ahat @ h2 + b2
    k_gemm2<<<(n + 127) / 128, 128>>>(W2, n);
    k_spmm2<<<(n / 2 + 7) / 8, 256>>>(b2, out, n);
}